// round 4
// baseline (speedup 1.0000x reference)
#include <cuda_runtime.h>
#include <cstdint>

#define SEQ   512
#define BATCH 256
#define CIN   64
#define HID   128
#define GATES 512   // 4*HID

// -------- scratch (static __device__ arrays; no allocation) --------
__device__ float g_xT[(size_t)SEQ * BATCH * CIN];     //  33 MB: x transposed to (S,B,C)
__device__ float g_xg[(size_t)SEQ * BATCH * GATES];   // 256 MB: pre-activations (S,B,4H)
__device__ float g_y1[(size_t)SEQ * BATCH * HID];     //  67 MB: layer-0 outputs (S,B,H)

typedef unsigned long long ull;

// -------- small helpers --------
__device__ __forceinline__ float fast_ex2(float x) {
    float y; asm("ex2.approx.f32 %0, %1;" : "=f"(y) : "f"(x)); return y;
}
__device__ __forceinline__ float fast_rcp(float x) {
    float y; asm("rcp.approx.f32 %0, %1;" : "=f"(y) : "f"(x)); return y;
}
__device__ __forceinline__ float sigmoid_f(float x) {
    float e = fast_ex2(-1.4426950408889634f * x);
    return fast_rcp(1.0f + e);
}
__device__ __forceinline__ float tanh_f(float x) {
    float ax = fabsf(x);
    float e  = fast_ex2(-2.8853900817779268f * ax);   // e^(-2|x|) in (0,1]
    float r  = fast_rcp(1.0f + e);
    float t  = fmaf(-2.0f * e, r, 1.0f);              // (1-e)/(1+e)
    return (x < 0.0f) ? -t : t;
}
__device__ __forceinline__ void ffma2(ull& acc, ull a, ull b) {
    asm("fma.rn.f32x2 %0, %1, %2, %0;" : "+l"(acc) : "l"(a), "l"(b));
}
__device__ __forceinline__ ull pack2(float lo, float hi) {
    ull r; asm("mov.b64 %0, {%1, %2};" : "=l"(r) : "f"(lo), "f"(hi)); return r;
}
__device__ __forceinline__ ull packr2(uint32_t lo, uint32_t hi) {
    ull r; asm("mov.b64 %0, {%1, %2};" : "=l"(r) : "r"(lo), "r"(hi)); return r;
}
__device__ __forceinline__ void unpack2(ull v, float& lo, float& hi) {
    asm("mov.b64 {%0, %1}, %2;" : "=f"(lo), "=f"(hi) : "l"(v));
}

// -------- kernel 0: alignment dummy (shifts ncu's profiled launch slot) --------
__global__ void k_nop() {}

// -------- kernel 1: transpose x (B,S,C) -> (S,B,C) --------
__global__ void k_transpose(const float* __restrict__ x) {
    int t = blockIdx.x * blockDim.x + threadIdx.x;   // enumerates (s,b,c), c fastest
    int c = t & (CIN - 1);
    int sb = t >> 6;
    int b = sb & (BATCH - 1);
    int s = sb >> 8;
    g_xT[t] = x[((size_t)b * SEQ + s) * CIN + c];
}

// -------- kernel 2/4: xg = A @ W^T + b1 + b2  (fp32, f32x2 accumulation) --------
template <int K, int ASEL>
__global__ __launch_bounds__(256) void k_gemm(const float* __restrict__ W,
                                              const float* __restrict__ b1,
                                              const float* __restrict__ b2) {
    const float* __restrict__ A = ASEL ? g_y1 : g_xT;

    __shared__ __align__(16) float As[16][128];
    __shared__ __align__(16) float Bs[16][64];

    const int tid   = threadIdx.x;
    const int mBase = blockIdx.x * 128;
    const int nBase = blockIdx.y * 64;

    const int aK = tid & 3;
    const int aM = tid >> 2;
    const int ty = tid >> 4;
    const int tx = tid & 15;
    const int m0 = ty * 8;
    const int n0 = tx * 4;

    ull acc[4][4];
#pragma unroll
    for (int i = 0; i < 4; i++)
#pragma unroll
        for (int j = 0; j < 4; j++) acc[i][j] = 0ULL;

    for (int kt = 0; kt < K; kt += 16) {
#pragma unroll
        for (int p = 0; p < 2; p++) {
            int row = aM + p * 64;
            float4 v = *reinterpret_cast<const float4*>(
                &A[((size_t)(mBase + row)) * K + kt + aK * 4]);
            As[aK * 4 + 0][row] = v.x;
            As[aK * 4 + 1][row] = v.y;
            As[aK * 4 + 2][row] = v.z;
            As[aK * 4 + 3][row] = v.w;
        }
        {
            float4 v = *reinterpret_cast<const float4*>(
                &W[((size_t)(nBase + aM)) * K + kt + aK * 4]);
            Bs[aK * 4 + 0][aM] = v.x;
            Bs[aK * 4 + 1][aM] = v.y;
            Bs[aK * 4 + 2][aM] = v.z;
            Bs[aK * 4 + 3][aM] = v.w;
        }
        __syncthreads();

#pragma unroll
        for (int kk = 0; kk < 16; kk++) {
            const ulonglong2* ap = reinterpret_cast<const ulonglong2*>(&As[kk][m0]);
            ulonglong2 a01 = ap[0];
            ulonglong2 a23 = ap[1];
            float4 b4 = *reinterpret_cast<const float4*>(&Bs[kk][n0]);
            ull bp0 = pack2(b4.x, b4.x);
            ull bp1 = pack2(b4.y, b4.y);
            ull bp2 = pack2(b4.z, b4.z);
            ull bp3 = pack2(b4.w, b4.w);
            ffma2(acc[0][0], a01.x, bp0); ffma2(acc[0][1], a01.x, bp1);
            ffma2(acc[0][2], a01.x, bp2); ffma2(acc[0][3], a01.x, bp3);
            ffma2(acc[1][0], a01.y, bp0); ffma2(acc[1][1], a01.y, bp1);
            ffma2(acc[1][2], a01.y, bp2); ffma2(acc[1][3], a01.y, bp3);
            ffma2(acc[2][0], a23.x, bp0); ffma2(acc[2][1], a23.x, bp1);
            ffma2(acc[2][2], a23.x, bp2); ffma2(acc[2][3], a23.x, bp3);
            ffma2(acc[3][0], a23.y, bp0); ffma2(acc[3][1], a23.y, bp1);
            ffma2(acc[3][2], a23.y, bp2); ffma2(acc[3][3], a23.y, bp3);
        }
        __syncthreads();
    }

    float bs[4];
#pragma unroll
    for (int j = 0; j < 4; j++) {
        int n = nBase + n0 + j;
        bs[j] = b1[n] + b2[n];
    }
#pragma unroll
    for (int i = 0; i < 4; i++) {
        float lo[4], hi[4];
#pragma unroll
        for (int j = 0; j < 4; j++) unpack2(acc[i][j], lo[j], hi[j]);
        size_t r0 = ((size_t)(mBase + m0 + 2 * i)) * GATES + nBase + n0;
        float4 v0 = make_float4(lo[0] + bs[0], lo[1] + bs[1], lo[2] + bs[2], lo[3] + bs[3]);
        float4 v1 = make_float4(hi[0] + bs[0], hi[1] + bs[1], hi[2] + bs[2], hi[3] + bs[3]);
        *reinterpret_cast<float4*>(&g_xg[r0])         = v0;
        *reinterpret_cast<float4*>(&g_xg[r0 + GATES]) = v1;
    }
}

// -------- kernel 3/5: LSTM recurrence (1024 threads, k-split, one barrier) --------
// 128 CTAs x 1024 threads; CTA owns 2 batch rows for all 512 steps.
// Thread j -> k-half (j&1) of gate ((j>>1)&3) of unit (j>>3).
// Each thread holds HALF a Whh row as bf16x2 (32 regs) -> 8 warps/SMSP for
// latency hiding with the same aggregate instruction count. Cross-half reduce
// is one shfl_xor(1); gate gather is 4 shfls per batch row within the 8-lane
// unit group. One __syncthreads per step (h double-buffered).
__global__ __launch_bounds__(1024, 1) void k_recur(const float* __restrict__ Whh,
                                                   float* __restrict__ out, int layer) {
    __shared__ __align__(16) float sh[2][2][HID];   // [parity][batch][unit]

    const int j    = threadIdx.x;
    const int b0   = blockIdx.x * 2;
    const int kh   = j & 1;          // k-half
    const int gsel = (j >> 1) & 3;   // 0:i 1:f 2:g 3:o
    const int u    = j >> 3;         // hidden unit 0..127
    const int row  = gsel * HID + u; // Whh row / gate column
    const int lane = j & 31;
    const int lb8  = lane & ~7;      // base lane of this unit's 8-lane group

    // activation constants: gate g uses tanh(x) = 2*sigmoid(2x)-1, others sigmoid
    const float s_in  = (gsel == 2) ? 2.0f : 1.0f;
    const float s_mul = (gsel == 2) ? 2.0f : 1.0f;
    const float s_add = (gsel == 2) ? -1.0f : 0.0f;

    // load + quantize my half weight row to bf16x2 (32 regs)
    uint32_t wq[32];
    {
        const float2* wrow =
            reinterpret_cast<const float2*>(Whh + (size_t)row * HID + kh * 64);
#pragma unroll
        for (int k2 = 0; k2 < 32; k2++) {
            float2 v = wrow[k2];
            uint32_t w;
            asm("cvt.rn.bf16x2.f32 %0, %1, %2;" : "=r"(w) : "f"(v.y), "f"(v.x)); // lo=v.x
            wq[k2] = w;
        }
    }

    if (j < 256) sh[0][j >> 7][j & (HID - 1)] = 0.0f;
    float c0 = 0.0f, c1 = 0.0f;

    const float* xgp = g_xg + (size_t)b0 * GATES + row;

    __syncthreads();

    int p = 0;
    for (int t = 0; t < SEQ; t++) {
        // xg loads issue here, consumed after the dot
        float xg0 = __ldg(xgp);
        float xg1 = __ldg(xgp + GATES);
        xgp += (size_t)BATCH * GATES;

        // half-dot(h_row[kh*64 .. +64), Whh_row) for both batch rows
        ull aA = 0ULL, aB = 0ULL, aC = 0ULL, aD = 0ULL;
        const ulonglong2* h0p =
            reinterpret_cast<const ulonglong2*>(&sh[p][0][kh * 64]);
        const ulonglong2* h1p =
            reinterpret_cast<const ulonglong2*>(&sh[p][1][kh * 64]);
#pragma unroll
        for (int g = 0; g < 16; g++) {   // 4 h-values per iteration
            ulonglong2 hv0 = h0p[g];
            ulonglong2 hv1 = h1p[g];
            uint32_t wa_ = wq[2 * g], wb_ = wq[2 * g + 1];
            ull wa = packr2(wa_ << 16, wa_ & 0xFFFF0000u);
            ull wb = packr2(wb_ << 16, wb_ & 0xFFFF0000u);
            ffma2(aA, wa, hv0.x);
            ffma2(aB, wb, hv0.y);
            ffma2(aC, wa, hv1.x);
            ffma2(aD, wb, hv1.y);
        }
        float l0, h0, l1, h1, l2, h2, l3, h3;
        unpack2(aA, l0, h0);
        unpack2(aB, l1, h1);
        unpack2(aC, l2, h2);
        unpack2(aD, l3, h3);
        float s0 = (l0 + h0) + (l1 + h1);
        float s1 = (l2 + h2) + (l3 + h3);
        // combine the two k-halves (adjacent lanes)
        s0 += __shfl_xor_sync(0xffffffffu, s0, 1);
        s1 += __shfl_xor_sync(0xffffffffu, s1, 1);

        float p0 = xg0 + s0;
        float p1 = xg1 + s1;

        // branchless activation (tanh via scaled sigmoid)
        float a0 = fmaf(s_mul, sigmoid_f(s_in * p0), s_add);
        float a1 = fmaf(s_mul, sigmoid_f(s_in * p1), s_add);

        // gather i,f,g,o of my unit (gates live at lb8 + 2*gate; kh lanes identical)
        float i0 = __shfl_sync(0xffffffffu, a0, lb8 + 0);
        float f0 = __shfl_sync(0xffffffffu, a0, lb8 + 2);
        float g0 = __shfl_sync(0xffffffffu, a0, lb8 + 4);
        float o0 = __shfl_sync(0xffffffffu, a0, lb8 + 6);
        float i1 = __shfl_sync(0xffffffffu, a1, lb8 + 0);
        float f1 = __shfl_sync(0xffffffffu, a1, lb8 + 2);
        float g1 = __shfl_sync(0xffffffffu, a1, lb8 + 4);
        float o1 = __shfl_sync(0xffffffffu, a1, lb8 + 6);

        // c/h update (redundant across the 8 lanes of each unit group)
        c0 = fmaf(f0, c0, i0 * g0);
        c1 = fmaf(f1, c1, i1 * g1);
        float hn0 = o0 * tanh_f(c0);
        float hn1 = o1 * tanh_f(c1);

        // write h to the other parity buffer (8 lanes write same value: benign)
        sh[p ^ 1][0][u] = hn0;
        sh[p ^ 1][1][u] = hn1;

        if (layer == 0) {
            if ((j & 7) == 0) {
                g_y1[((size_t)t * BATCH + b0) * HID + u]     = hn0;
                g_y1[((size_t)t * BATCH + b0 + 1) * HID + u] = hn1;
            }
        } else if (t == SEQ - 1 && (j & 7) == 0) {
            out[(size_t)b0 * HID + u]       = hn0;
            out[(size_t)(b0 + 1) * HID + u] = hn1;
        }

        __syncthreads();
        p ^= 1;
    }
}

// -------- launch --------
extern "C" void kernel_launch(void* const* d_in, const int* in_sizes, int n_in,
                              void* d_out, int out_size) {
    const float* x    = (const float*)d_in[0];
    const float* Wih0 = (const float*)d_in[1];
    const float* Whh0 = (const float*)d_in[2];
    const float* bih0 = (const float*)d_in[3];
    const float* bhh0 = (const float*)d_in[4];
    const float* Wih1 = (const float*)d_in[5];
    const float* Whh1 = (const float*)d_in[6];
    const float* bih1 = (const float*)d_in[7];
    const float* bhh1 = (const float*)d_in[8];
    float* out = (float*)d_out;

    // 0. alignment dummy so ncu's fixed profile slot lands on k_recur (layer 0)
    k_nop<<<1, 1>>>();
    // 1. x (B,S,C) -> (S,B,C)
    k_transpose<<<(SEQ * BATCH * CIN) / 256, 256>>>(x);
    // 2. xg = xT @ Wih0^T + bih0 + bhh0
    k_gemm<CIN, 0><<<dim3((SEQ * BATCH) / 128, GATES / 64), 256>>>(Wih0, bih0, bhh0);
    // 3. layer-0 recurrence -> g_y1
    k_recur<<<BATCH / 2, 1024>>>(Whh0, nullptr, 0);
    // 4. xg = y1 @ Wih1^T + bih1 + bhh1
    k_gemm<HID, 1><<<dim3((SEQ * BATCH) / 128, GATES / 64), 256>>>(Wih1, bih1, bhh1);
    // 5. layer-1 recurrence -> out (last timestep only)
    k_recur<<<BATCH / 2, 1024>>>(Whh1, out, 1);
}

// round 5
// speedup vs baseline: 1.4639x; 1.4639x over previous
#include <cuda_runtime.h>
#include <cstdint>

#define SEQ   512
#define BATCH 256
#define CIN   64
#define HID   128
#define GATES 512   // 4*HID

// -------- scratch (static __device__ arrays; no allocation) --------
__device__ float g_xT[(size_t)SEQ * BATCH * CIN];     //  33 MB: x transposed to (S,B,C)
__device__ float g_xg[(size_t)SEQ * BATCH * GATES];   // 256 MB: pre-activations (S,B,4H)
__device__ float g_y1[(size_t)SEQ * BATCH * HID];     //  67 MB: layer-0 outputs (S,B,H)

typedef unsigned long long ull;

// -------- small helpers --------
__device__ __forceinline__ float fast_ex2(float x) {
    float y; asm("ex2.approx.f32 %0, %1;" : "=f"(y) : "f"(x)); return y;
}
__device__ __forceinline__ float fast_rcp(float x) {
    float y; asm("rcp.approx.f32 %0, %1;" : "=f"(y) : "f"(x)); return y;
}
__device__ __forceinline__ float sigmoid_f(float x) {
    float e = fast_ex2(-1.4426950408889634f * x);
    return fast_rcp(1.0f + e);
}
__device__ __forceinline__ float tanh_f(float x) {
    float ax = fabsf(x);
    float e  = fast_ex2(-2.8853900817779268f * ax);   // e^(-2|x|) in (0,1]
    float r  = fast_rcp(1.0f + e);
    float t  = fmaf(-2.0f * e, r, 1.0f);              // (1-e)/(1+e)
    return (x < 0.0f) ? -t : t;
}
__device__ __forceinline__ void ffma2(ull& acc, ull a, ull b) {
    asm("fma.rn.f32x2 %0, %1, %2, %0;" : "+l"(acc) : "l"(a), "l"(b));
}
__device__ __forceinline__ ull pack2(float lo, float hi) {
    ull r; asm("mov.b64 %0, {%1, %2};" : "=l"(r) : "f"(lo), "f"(hi)); return r;
}
__device__ __forceinline__ ull packr2(uint32_t lo, uint32_t hi) {
    ull r; asm("mov.b64 %0, {%1, %2};" : "=l"(r) : "r"(lo), "r"(hi)); return r;
}
__device__ __forceinline__ void unpack2(ull v, float& lo, float& hi) {
    asm("mov.b64 {%0, %1}, %2;" : "=f"(lo), "=f"(hi) : "l"(v));
}
__device__ __forceinline__ uint32_t smem_u32(const void* p) {
    return (uint32_t)__cvta_generic_to_shared(p);
}
__device__ __forceinline__ void cp_async4(uint32_t dst, const float* src) {
    asm volatile("cp.async.ca.shared.global [%0], [%1], 4;" :: "r"(dst), "l"(src));
}
#define CP_COMMIT() asm volatile("cp.async.commit_group;" ::: "memory")
#define CP_WAIT0()  asm volatile("cp.async.wait_group 0;" ::: "memory")

// -------- kernel 0: alignment dummy (shifts ncu's profiled launch slot) --------
__global__ void k_nop() {}

// -------- kernel 1: transpose x (B,S,C) -> (S,B,C) --------
__global__ void k_transpose(const float* __restrict__ x) {
    int t = blockIdx.x * blockDim.x + threadIdx.x;   // enumerates (s,b,c), c fastest
    int c = t & (CIN - 1);
    int sb = t >> 6;
    int b = sb & (BATCH - 1);
    int s = sb >> 8;
    g_xT[t] = x[((size_t)b * SEQ + s) * CIN + c];
}

// -------- kernel 2/4: xg = A @ W^T + b1 + b2  (fp32, f32x2 accumulation) --------
template <int K, int ASEL>
__global__ __launch_bounds__(256) void k_gemm(const float* __restrict__ W,
                                              const float* __restrict__ b1,
                                              const float* __restrict__ b2) {
    const float* __restrict__ A = ASEL ? g_y1 : g_xT;

    __shared__ __align__(16) float As[16][128];
    __shared__ __align__(16) float Bs[16][64];

    const int tid   = threadIdx.x;
    const int mBase = blockIdx.x * 128;
    const int nBase = blockIdx.y * 64;

    const int aK = tid & 3;
    const int aM = tid >> 2;
    const int ty = tid >> 4;
    const int tx = tid & 15;
    const int m0 = ty * 8;
    const int n0 = tx * 4;

    ull acc[4][4];
#pragma unroll
    for (int i = 0; i < 4; i++)
#pragma unroll
        for (int j = 0; j < 4; j++) acc[i][j] = 0ULL;

    for (int kt = 0; kt < K; kt += 16) {
#pragma unroll
        for (int p = 0; p < 2; p++) {
            int row = aM + p * 64;
            float4 v = *reinterpret_cast<const float4*>(
                &A[((size_t)(mBase + row)) * K + kt + aK * 4]);
            As[aK * 4 + 0][row] = v.x;
            As[aK * 4 + 1][row] = v.y;
            As[aK * 4 + 2][row] = v.z;
            As[aK * 4 + 3][row] = v.w;
        }
        {
            float4 v = *reinterpret_cast<const float4*>(
                &W[((size_t)(nBase + aM)) * K + kt + aK * 4]);
            Bs[aK * 4 + 0][aM] = v.x;
            Bs[aK * 4 + 1][aM] = v.y;
            Bs[aK * 4 + 2][aM] = v.z;
            Bs[aK * 4 + 3][aM] = v.w;
        }
        __syncthreads();

#pragma unroll
        for (int kk = 0; kk < 16; kk++) {
            const ulonglong2* ap = reinterpret_cast<const ulonglong2*>(&As[kk][m0]);
            ulonglong2 a01 = ap[0];
            ulonglong2 a23 = ap[1];
            float4 b4 = *reinterpret_cast<const float4*>(&Bs[kk][n0]);
            ull bp0 = pack2(b4.x, b4.x);
            ull bp1 = pack2(b4.y, b4.y);
            ull bp2 = pack2(b4.z, b4.z);
            ull bp3 = pack2(b4.w, b4.w);
            ffma2(acc[0][0], a01.x, bp0); ffma2(acc[0][1], a01.x, bp1);
            ffma2(acc[0][2], a01.x, bp2); ffma2(acc[0][3], a01.x, bp3);
            ffma2(acc[1][0], a01.y, bp0); ffma2(acc[1][1], a01.y, bp1);
            ffma2(acc[1][2], a01.y, bp2); ffma2(acc[1][3], a01.y, bp3);
            ffma2(acc[2][0], a23.x, bp0); ffma2(acc[2][1], a23.x, bp1);
            ffma2(acc[2][2], a23.x, bp2); ffma2(acc[2][3], a23.x, bp3);
            ffma2(acc[3][0], a23.y, bp0); ffma2(acc[3][1], a23.y, bp1);
            ffma2(acc[3][2], a23.y, bp2); ffma2(acc[3][3], a23.y, bp3);
        }
        __syncthreads();
    }

    float bs[4];
#pragma unroll
    for (int j = 0; j < 4; j++) {
        int n = nBase + n0 + j;
        bs[j] = b1[n] + b2[n];
    }
#pragma unroll
    for (int i = 0; i < 4; i++) {
        float lo[4], hi[4];
#pragma unroll
        for (int j = 0; j < 4; j++) unpack2(acc[i][j], lo[j], hi[j]);
        size_t r0 = ((size_t)(mBase + m0 + 2 * i)) * GATES + nBase + n0;
        float4 v0 = make_float4(lo[0] + bs[0], lo[1] + bs[1], lo[2] + bs[2], lo[3] + bs[3]);
        float4 v1 = make_float4(hi[0] + bs[0], hi[1] + bs[1], hi[2] + bs[2], hi[3] + bs[3]);
        *reinterpret_cast<float4*>(&g_xg[r0])         = v0;
        *reinterpret_cast<float4*>(&g_xg[r0 + GATES]) = v1;
    }
}

// -------- kernel 3/5: LSTM recurrence (cp.async xg staging, one barrier) --------
// 128 CTAs x 512 threads; CTA owns 2 batch rows. Thread j = gate (j&3) of unit
// (j>>2); Whh row in registers (bf16x2, 64 regs). xg for step t+1 is staged
// into a double-buffered SMEM tile via cp.async issued at the TOP of step t and
// waited at the BOTTOM (full-step latency window, register-free) — so per-step
// DRAM completion jitter no longer sits on the critical path.
__global__ __launch_bounds__(512) void k_recur(const float* __restrict__ Whh,
                                               float* __restrict__ out, int layer) {
    __shared__ __align__(16) float  sh[2][2][HID];     // [parity][batch][unit]
    __shared__ __align__(16) float2 sxg[2][GATES];     // [buf][gate] = (row b0, row b0+1)

    const int j    = threadIdx.x;
    const int b0   = blockIdx.x * 2;
    const int gsel = j & 3;          // 0:i 1:f 2:g 3:o
    const int u    = j >> 2;         // hidden unit 0..127
    const int row  = gsel * HID + u; // Whh row / gate column
    const int lane = j & 31;
    const int lbase = lane & ~3;

    // activation constants: gate g uses tanh(x) = 2*sigmoid(2x)-1, others sigmoid
    const float s_in  = (gsel == 2) ? 2.0f : 1.0f;
    const float s_mul = (gsel == 2) ? 2.0f : 1.0f;
    const float s_add = (gsel == 2) ? -1.0f : 0.0f;

    // load + quantize my weight row to bf16x2 (64 regs)
    uint32_t wq[64];
    {
        const float2* wrow = reinterpret_cast<const float2*>(Whh + (size_t)row * HID);
#pragma unroll
        for (int k2 = 0; k2 < 64; k2++) {
            float2 v = wrow[k2];
            uint32_t w;
            asm("cvt.rn.bf16x2.f32 %0, %1, %2;" : "=r"(w) : "f"(v.y), "f"(v.x)); // lo=v.x
            wq[k2] = w;
        }
    }

    if (j < 256) sh[0][j >> 7][j & (HID - 1)] = 0.0f;
    float c0 = 0.0f, c1 = 0.0f;

    // staging: thread j prefetches gate column j for both batch rows (4B each,
    // coalesced across the warp in gmem).
    const float*  sgp0   = g_xg + (size_t)b0 * GATES + j;           // row b0, gate j
    const uint32_t dstA0 = smem_u32(&sxg[0][j].x);
    const uint32_t dstA1 = smem_u32(&sxg[0][j].y);
    const uint32_t dstB0 = smem_u32(&sxg[1][j].x);
    const uint32_t dstB1 = smem_u32(&sxg[1][j].y);

    // prologue: stage t=0 into buf 0
    cp_async4(dstA0, sgp0);
    cp_async4(dstA1, sgp0 + GATES);
    CP_COMMIT();
    CP_WAIT0();
    __syncthreads();

    int p = 0;
    for (int t = 0; t < SEQ; t++) {
        // issue prefetch of xg for t+1 into the other buffer (full-step window)
        if (t + 1 < SEQ) {
            const float* src = sgp0 + (size_t)(t + 1) * BATCH * GATES;
            if ((t & 1) == 0) {
                cp_async4(dstB0, src);
                cp_async4(dstB1, src + GATES);
            } else {
                cp_async4(dstA0, src);
                cp_async4(dstA1, src + GATES);
            }
        }
        CP_COMMIT();

        // dot(h_row, Whh_row) for both batch rows; 4 independent chains
        ull aA = 0ULL, aB = 0ULL, aC = 0ULL, aD = 0ULL;
        const ulonglong2* h0p = reinterpret_cast<const ulonglong2*>(sh[p][0]);
        const ulonglong2* h1p = reinterpret_cast<const ulonglong2*>(sh[p][1]);
#pragma unroll
        for (int g = 0; g < 32; g++) {   // 4 h-values per iteration
            ulonglong2 hv0 = h0p[g];
            ulonglong2 hv1 = h1p[g];
            uint32_t wa_ = wq[2 * g], wb_ = wq[2 * g + 1];
            ull wa = packr2(wa_ << 16, wa_ & 0xFFFF0000u);
            ull wb = packr2(wb_ << 16, wb_ & 0xFFFF0000u);
            ffma2(aA, wa, hv0.x);
            ffma2(aB, wb, hv0.y);
            ffma2(aC, wa, hv1.x);
            ffma2(aD, wb, hv1.y);
        }
        float l0, h0, l1, h1, l2, h2, l3, h3;
        unpack2(aA, l0, h0);
        unpack2(aB, l1, h1);
        unpack2(aC, l2, h2);
        unpack2(aD, l3, h3);

        // xg for this step from the staged buffer (one LDS.64)
        float2 xg = sxg[t & 1][row];

        float p0 = xg.x + ((l0 + h0) + (l1 + h1));
        float p1 = xg.y + ((l2 + h2) + (l3 + h3));

        // branchless activation (tanh via scaled sigmoid)
        float a0 = fmaf(s_mul, sigmoid_f(s_in * p0), s_add);
        float a1 = fmaf(s_mul, sigmoid_f(s_in * p1), s_add);

        // gather i,f,g,o of my unit from adjacent lanes
        float i0 = __shfl_sync(0xffffffffu, a0, lbase + 0);
        float f0 = __shfl_sync(0xffffffffu, a0, lbase + 1);
        float g0 = __shfl_sync(0xffffffffu, a0, lbase + 2);
        float o0 = __shfl_sync(0xffffffffu, a0, lbase + 3);
        float i1 = __shfl_sync(0xffffffffu, a1, lbase + 0);
        float f1 = __shfl_sync(0xffffffffu, a1, lbase + 1);
        float g1 = __shfl_sync(0xffffffffu, a1, lbase + 2);
        float o1 = __shfl_sync(0xffffffffu, a1, lbase + 3);

        // c/h update (computed redundantly in the 4 lanes of each unit group)
        c0 = fmaf(f0, c0, i0 * g0);
        c1 = fmaf(f1, c1, i1 * g1);
        float hn0 = o0 * tanh_f(c0);
        float hn1 = o1 * tanh_f(c1);

        // write h to the other parity buffer (4 lanes write same value: benign)
        sh[p ^ 1][0][u] = hn0;
        sh[p ^ 1][1][u] = hn1;

        if (layer == 0) {
            if (gsel == 0) {
                g_y1[((size_t)t * BATCH + b0) * HID + u]     = hn0;
                g_y1[((size_t)t * BATCH + b0 + 1) * HID + u] = hn1;
            }
        } else if (t == SEQ - 1 && gsel == 0) {
            out[(size_t)b0 * HID + u]       = hn0;
            out[(size_t)(b0 + 1) * HID + u] = hn1;
        }

        // ensure next step's staged xg has landed, then one barrier
        CP_WAIT0();
        __syncthreads();
        p ^= 1;
    }
}

// -------- launch --------
extern "C" void kernel_launch(void* const* d_in, const int* in_sizes, int n_in,
                              void* d_out, int out_size) {
    const float* x    = (const float*)d_in[0];
    const float* Wih0 = (const float*)d_in[1];
    const float* Whh0 = (const float*)d_in[2];
    const float* bih0 = (const float*)d_in[3];
    const float* bhh0 = (const float*)d_in[4];
    const float* Wih1 = (const float*)d_in[5];
    const float* Whh1 = (const float*)d_in[6];
    const float* bih1 = (const float*)d_in[7];
    const float* bhh1 = (const float*)d_in[8];
    float* out = (float*)d_out;

    // 0. alignment dummy so ncu's fixed profile slot lands on k_recur (layer 0)
    k_nop<<<1, 1>>>();
    // 1. x (B,S,C) -> (S,B,C)
    k_transpose<<<(SEQ * BATCH * CIN) / 256, 256>>>(x);
    // 2. xg = xT @ Wih0^T + bih0 + bhh0
    k_gemm<CIN, 0><<<dim3((SEQ * BATCH) / 128, GATES / 64), 256>>>(Wih0, bih0, bhh0);
    // 3. layer-0 recurrence -> g_y1
    k_recur<<<BATCH / 2, 512>>>(Whh0, nullptr, 0);
    // 4. xg = y1 @ Wih1^T + bih1 + bhh1
    k_gemm<HID, 1><<<dim3((SEQ * BATCH) / 128, GATES / 64), 256>>>(Wih1, bih1, bhh1);
    // 5. layer-1 recurrence -> out (last timestep only)
    k_recur<<<BATCH / 2, 512>>>(Whh1, out, 1);
}

// round 6
// speedup vs baseline: 1.6681x; 1.1395x over previous
#include <cuda_runtime.h>
#include <cstdint>

#define SEQ   512
#define BATCH 256
#define CIN   64
#define HID   128
#define GATES 512   // 4*HID
#define QPAD  36    // padded quarter pitch (32 + 4) -> bank shift 4 per quarter

// -------- scratch (static __device__ arrays; no allocation) --------
__device__ float g_xT[(size_t)SEQ * BATCH * CIN];     //  33 MB: x transposed to (S,B,C)
__device__ float g_xg[(size_t)SEQ * BATCH * GATES];   // 256 MB: pre-activations (S,B,4H)
__device__ float g_y1[(size_t)SEQ * BATCH * HID];     //  67 MB: layer-0 outputs (S,B,H)

typedef unsigned long long ull;

// -------- small helpers --------
__device__ __forceinline__ float fast_ex2(float x) {
    float y; asm("ex2.approx.f32 %0, %1;" : "=f"(y) : "f"(x)); return y;
}
__device__ __forceinline__ float fast_rcp(float x) {
    float y; asm("rcp.approx.f32 %0, %1;" : "=f"(y) : "f"(x)); return y;
}
__device__ __forceinline__ float sigmoid_f(float x) {
    float e = fast_ex2(-1.4426950408889634f * x);
    return fast_rcp(1.0f + e);
}
__device__ __forceinline__ float tanh_f(float x) {
    float ax = fabsf(x);
    float e  = fast_ex2(-2.8853900817779268f * ax);   // e^(-2|x|) in (0,1]
    float r  = fast_rcp(1.0f + e);
    float t  = fmaf(-2.0f * e, r, 1.0f);              // (1-e)/(1+e)
    return (x < 0.0f) ? -t : t;
}
__device__ __forceinline__ void ffma2(ull& acc, ull a, ull b) {
    asm("fma.rn.f32x2 %0, %1, %2, %0;" : "+l"(acc) : "l"(a), "l"(b));
}
__device__ __forceinline__ ull pack2(float lo, float hi) {
    ull r; asm("mov.b64 %0, {%1, %2};" : "=l"(r) : "f"(lo), "f"(hi)); return r;
}
__device__ __forceinline__ ull packr2(uint32_t lo, uint32_t hi) {
    ull r; asm("mov.b64 %0, {%1, %2};" : "=l"(r) : "r"(lo), "r"(hi)); return r;
}
__device__ __forceinline__ void unpack2(ull v, float& lo, float& hi) {
    asm("mov.b64 {%0, %1}, %2;" : "=f"(lo), "=f"(hi) : "l"(v));
}
__device__ __forceinline__ uint32_t smem_u32(const void* p) {
    return (uint32_t)__cvta_generic_to_shared(p);
}
__device__ __forceinline__ void cp_async4(uint32_t dst, const float* src) {
    asm volatile("cp.async.ca.shared.global [%0], [%1], 4;" :: "r"(dst), "l"(src));
}
#define CP_COMMIT() asm volatile("cp.async.commit_group;" ::: "memory")
#define CP_WAIT0()  asm volatile("cp.async.wait_group 0;" ::: "memory")

// -------- kernel 0: alignment dummy (shifts ncu's profiled launch slot) --------
__global__ void k_nop() {}

// -------- kernel 1: transpose x (B,S,C) -> (S,B,C) --------
__global__ void k_transpose(const float* __restrict__ x) {
    int t = blockIdx.x * blockDim.x + threadIdx.x;   // enumerates (s,b,c), c fastest
    int c = t & (CIN - 1);
    int sb = t >> 6;
    int b = sb & (BATCH - 1);
    int s = sb >> 8;
    g_xT[t] = x[((size_t)b * SEQ + s) * CIN + c];
}

// -------- kernel 2/4: xg = A @ W^T + b1 + b2  (fp32, f32x2 accumulation) --------
template <int K, int ASEL>
__global__ __launch_bounds__(256) void k_gemm(const float* __restrict__ W,
                                              const float* __restrict__ b1,
                                              const float* __restrict__ b2) {
    const float* __restrict__ A = ASEL ? g_y1 : g_xT;

    __shared__ __align__(16) float As[16][128];
    __shared__ __align__(16) float Bs[16][64];

    const int tid   = threadIdx.x;
    const int mBase = blockIdx.x * 128;
    const int nBase = blockIdx.y * 64;

    const int aK = tid & 3;
    const int aM = tid >> 2;
    const int ty = tid >> 4;
    const int tx = tid & 15;
    const int m0 = ty * 8;
    const int n0 = tx * 4;

    ull acc[4][4];
#pragma unroll
    for (int i = 0; i < 4; i++)
#pragma unroll
        for (int j = 0; j < 4; j++) acc[i][j] = 0ULL;

    for (int kt = 0; kt < K; kt += 16) {
#pragma unroll
        for (int p = 0; p < 2; p++) {
            int row = aM + p * 64;
            float4 v = *reinterpret_cast<const float4*>(
                &A[((size_t)(mBase + row)) * K + kt + aK * 4]);
            As[aK * 4 + 0][row] = v.x;
            As[aK * 4 + 1][row] = v.y;
            As[aK * 4 + 2][row] = v.z;
            As[aK * 4 + 3][row] = v.w;
        }
        {
            float4 v = *reinterpret_cast<const float4*>(
                &W[((size_t)(nBase + aM)) * K + kt + aK * 4]);
            Bs[aK * 4 + 0][aM] = v.x;
            Bs[aK * 4 + 1][aM] = v.y;
            Bs[aK * 4 + 2][aM] = v.z;
            Bs[aK * 4 + 3][aM] = v.w;
        }
        __syncthreads();

#pragma unroll
        for (int kk = 0; kk < 16; kk++) {
            const ulonglong2* ap = reinterpret_cast<const ulonglong2*>(&As[kk][m0]);
            ulonglong2 a01 = ap[0];
            ulonglong2 a23 = ap[1];
            float4 b4 = *reinterpret_cast<const float4*>(&Bs[kk][n0]);
            ull bp0 = pack2(b4.x, b4.x);
            ull bp1 = pack2(b4.y, b4.y);
            ull bp2 = pack2(b4.z, b4.z);
            ull bp3 = pack2(b4.w, b4.w);
            ffma2(acc[0][0], a01.x, bp0); ffma2(acc[0][1], a01.x, bp1);
            ffma2(acc[0][2], a01.x, bp2); ffma2(acc[0][3], a01.x, bp3);
            ffma2(acc[1][0], a01.y, bp0); ffma2(acc[1][1], a01.y, bp1);
            ffma2(acc[1][2], a01.y, bp2); ffma2(acc[1][3], a01.y, bp3);
            ffma2(acc[2][0], a23.x, bp0); ffma2(acc[2][1], a23.x, bp1);
            ffma2(acc[2][2], a23.x, bp2); ffma2(acc[2][3], a23.x, bp3);
            ffma2(acc[3][0], a23.y, bp0); ffma2(acc[3][1], a23.y, bp1);
            ffma2(acc[3][2], a23.y, bp2); ffma2(acc[3][3], a23.y, bp3);
        }
        __syncthreads();
    }

    float bs[4];
#pragma unroll
    for (int j = 0; j < 4; j++) {
        int n = nBase + n0 + j;
        bs[j] = b1[n] + b2[n];
    }
#pragma unroll
    for (int i = 0; i < 4; i++) {
        float lo[4], hi[4];
#pragma unroll
        for (int j = 0; j < 4; j++) unpack2(acc[i][j], lo[j], hi[j]);
        size_t r0 = ((size_t)(mBase + m0 + 2 * i)) * GATES + nBase + n0;
        float4 v0 = make_float4(lo[0] + bs[0], lo[1] + bs[1], lo[2] + bs[2], lo[3] + bs[3]);
        float4 v1 = make_float4(hi[0] + bs[0], hi[1] + bs[1], hi[2] + bs[2], hi[3] + bs[3]);
        *reinterpret_cast<float4*>(&g_xg[r0])         = v0;
        *reinterpret_cast<float4*>(&g_xg[r0 + GATES]) = v1;
    }
}

// -------- kernel 3/5: LSTM recurrence (k-quartered, 4 gates/thread) --------
// 128 CTAs x 512 threads; CTA owns 2 batch rows.
// Thread j: unit u = j>>2, k-quarter kq = lane&3. The thread holds ALL FOUR
// gate rows of its unit over its 32-wide k-quarter as bf16x2 (64 regs).
// -> per warp only 16 LDS.128/step (was 64): smem crossbar traffic /4.
// Cross-quarter reduce = 2 in-quad shfl_xor. Whole i/f/g/o->c->h tail is
// in-thread (no gate-gather shfls). h double-buffered; one barrier per step.
__global__ __launch_bounds__(512) void k_recur(const float* __restrict__ Whh,
                                               float* __restrict__ out, int layer) {
    __shared__ __align__(16) float  sh[2][2][4][QPAD];   // [parity][batch][quarter][32+pad]
    __shared__ __align__(16) float2 sxg[2][GATES];       // [buf][gate] = (b0, b1)

    const int j    = threadIdx.x;
    const int b0   = blockIdx.x * 2;
    const int lane = j & 31;
    const int kq   = lane & 3;       // k-quarter
    const int u    = j >> 2;         // hidden unit 0..127

    // weights: 4 gate rows x quarter-k as bf16x2 (4 x 16 = 64 regs)
    uint32_t wq[4][16];
#pragma unroll
    for (int g = 0; g < 4; g++) {
        const float2* wrow = reinterpret_cast<const float2*>(
            Whh + (size_t)(g * HID + u) * HID + kq * 32);
#pragma unroll
        for (int w = 0; w < 16; w++) {
            float2 v = wrow[w];
            uint32_t wv;
            asm("cvt.rn.bf16x2.f32 %0, %1, %2;" : "=r"(wv) : "f"(v.y), "f"(v.x)); // lo=v.x
            wq[g][w] = wv;
        }
    }

    // zero h buffers (parity 0), incl. pads
    for (int i = j; i < 2 * 2 * 4 * QPAD; i += 512)
        reinterpret_cast<float*>(sh)[i] = 0.0f;
    float c0 = 0.0f, c1 = 0.0f;

    // xg staging: thread j stages gate column j for both batch rows
    const float*   sgp0  = g_xg + (size_t)b0 * GATES + j;
    const uint32_t dstA0 = smem_u32(&sxg[0][j].x);
    const uint32_t dstA1 = smem_u32(&sxg[0][j].y);
    const uint32_t dstB0 = smem_u32(&sxg[1][j].x);
    const uint32_t dstB1 = smem_u32(&sxg[1][j].y);

    cp_async4(dstA0, sgp0);
    cp_async4(dstA1, sgp0 + GATES);
    CP_COMMIT();
    CP_WAIT0();
    __syncthreads();

    int p = 0;
    for (int t = 0; t < SEQ; t++) {
        // prefetch xg for t+1 into the other buffer (full-step latency window)
        if (t + 1 < SEQ) {
            const float* src = sgp0 + (size_t)(t + 1) * BATCH * GATES;
            if ((t & 1) == 0) {
                cp_async4(dstB0, src);
                cp_async4(dstB1, src + GATES);
            } else {
                cp_async4(dstA0, src);
                cp_async4(dstA1, src + GATES);
            }
        }
        CP_COMMIT();

        // quarter-dot: 4 gates x 2 batch, k-pair packed FFMA2 (8 acc chains)
        ull acc[4][2];
#pragma unroll
        for (int g = 0; g < 4; g++) { acc[g][0] = 0ULL; acc[g][1] = 0ULL; }

        const ulonglong2* h0p =
            reinterpret_cast<const ulonglong2*>(&sh[p][0][kq][0]);
        const ulonglong2* h1p =
            reinterpret_cast<const ulonglong2*>(&sh[p][1][kq][0]);
#pragma unroll
        for (int w2 = 0; w2 < 8; w2++) {     // 4 k-values per iter
            ulonglong2 hv0 = h0p[w2];
            ulonglong2 hv1 = h1p[w2];
#pragma unroll
            for (int g = 0; g < 4; g++) {
                uint32_t wA = wq[g][2 * w2], wB = wq[g][2 * w2 + 1];
                ull wa = packr2(wA << 16, wA & 0xFFFF0000u);
                ull wb = packr2(wB << 16, wB & 0xFFFF0000u);
                ffma2(acc[g][0], wa, hv0.x);
                ffma2(acc[g][0], wb, hv0.y);
                ffma2(acc[g][1], wa, hv1.x);
                ffma2(acc[g][1], wb, hv1.y);
            }
        }

        // horizontal + cross-quarter (quad) reduction, then + xg
        float pre[4][2];
#pragma unroll
        for (int g = 0; g < 4; g++) {
#pragma unroll
            for (int b = 0; b < 2; b++) {
                float lo, hi;
                unpack2(acc[g][b], lo, hi);
                float v = lo + hi;
                v += __shfl_xor_sync(0xffffffffu, v, 1);
                v += __shfl_xor_sync(0xffffffffu, v, 2);
                pre[g][b] = v;
            }
        }
        const int buf = t & 1;
#pragma unroll
        for (int g = 0; g < 4; g++) {
            float2 xgv = sxg[buf][g * HID + u];
            pre[g][0] += xgv.x;
            pre[g][1] += xgv.y;
        }

        // activations + state update (fully in-thread; redundant across quad)
        float i0 = sigmoid_f(pre[0][0]), i1 = sigmoid_f(pre[0][1]);
        float f0 = sigmoid_f(pre[1][0]), f1 = sigmoid_f(pre[1][1]);
        float g0 = tanh_f(pre[2][0]),    g1 = tanh_f(pre[2][1]);
        float o0 = sigmoid_f(pre[3][0]), o1 = sigmoid_f(pre[3][1]);
        c0 = fmaf(f0, c0, i0 * g0);
        c1 = fmaf(f1, c1, i1 * g1);
        float hn0 = o0 * tanh_f(c0);
        float hn1 = o1 * tanh_f(c1);

        // lane kq==0 of each quad writes the unit's h (and y1/out)
        if (kq == 0) {
            sh[p ^ 1][0][u >> 5][u & 31] = hn0;
            sh[p ^ 1][1][u >> 5][u & 31] = hn1;
            if (layer == 0) {
                g_y1[((size_t)t * BATCH + b0) * HID + u]     = hn0;
                g_y1[((size_t)t * BATCH + b0 + 1) * HID + u] = hn1;
            } else if (t == SEQ - 1) {
                out[(size_t)b0 * HID + u]       = hn0;
                out[(size_t)(b0 + 1) * HID + u] = hn1;
            }
        }

        CP_WAIT0();
        __syncthreads();
        p ^= 1;
    }
}

// -------- launch --------
extern "C" void kernel_launch(void* const* d_in, const int* in_sizes, int n_in,
                              void* d_out, int out_size) {
    const float* x    = (const float*)d_in[0];
    const float* Wih0 = (const float*)d_in[1];
    const float* Whh0 = (const float*)d_in[2];
    const float* bih0 = (const float*)d_in[3];
    const float* bhh0 = (const float*)d_in[4];
    const float* Wih1 = (const float*)d_in[5];
    const float* Whh1 = (const float*)d_in[6];
    const float* bih1 = (const float*)d_in[7];
    const float* bhh1 = (const float*)d_in[8];
    float* out = (float*)d_out;

    // 0. alignment dummy so ncu's fixed profile slot lands on k_recur (layer 0)
    k_nop<<<1, 1>>>();
    // 1. x (B,S,C) -> (S,B,C)
    k_transpose<<<(SEQ * BATCH * CIN) / 256, 256>>>(x);
    // 2. xg = xT @ Wih0^T + bih0 + bhh0
    k_gemm<CIN, 0><<<dim3((SEQ * BATCH) / 128, GATES / 64), 256>>>(Wih0, bih0, bhh0);
    // 3. layer-0 recurrence -> g_y1
    k_recur<<<BATCH / 2, 512>>>(Whh0, nullptr, 0);
    // 4. xg = y1 @ Wih1^T + bih1 + bhh1
    k_gemm<HID, 1><<<dim3((SEQ * BATCH) / 128, GATES / 64), 256>>>(Wih1, bih1, bhh1);
    // 5. layer-1 recurrence -> out (last timestep only)
    k_recur<<<BATCH / 2, 512>>>(Whh1, out, 1);
}